// round 6
// baseline (speedup 1.0000x reference)
#include <cuda_runtime.h>

#define D_DIM 64
#define H_DIM 256
#define W_DIM 256
#define PLANE (H_DIM * W_DIM)
#define D_CHUNK 8   // outputs per block along D (4 shared pairs)

// compare-exchange: a=min, b=max
__device__ __forceinline__ void s2(float& a, float& b) {
    float t = fminf(a, b);
    b = fmaxf(a, b);
    a = t;
}

// Optimal 9-input sorting network: 25 comparators, depth 7.
__device__ __forceinline__ void sort9(float* v) {
    s2(v[0],v[3]); s2(v[1],v[7]); s2(v[2],v[5]); s2(v[4],v[8]);
    s2(v[0],v[7]); s2(v[2],v[4]); s2(v[3],v[8]); s2(v[5],v[6]);
    s2(v[0],v[2]); s2(v[1],v[3]); s2(v[4],v[5]); s2(v[7],v[8]);
    s2(v[1],v[4]); s2(v[3],v[6]); s2(v[5],v[7]);
    s2(v[0],v[1]); s2(v[2],v[4]); s2(v[3],v[5]); s2(v[6],v[8]);
    s2(v[2],v[3]); s2(v[4],v[5]); s2(v[6],v[7]);
    s2(v[1],v[2]); s2(v[3],v[4]); s2(v[5],v[6]);
}

// ---- Batcher odd-even merges of two sorted arrays ----
__device__ __forceinline__ void merge11(const float* a, const float* b, float* c) {
    c[0] = a[0]; c[1] = b[0]; s2(c[0], c[1]);
}
__device__ __forceinline__ void merge22(const float* a, const float* b, float* c) {
    float ae[1] = {a[0]}, be[1] = {b[0]}, ao[1] = {a[1]}, bo[1] = {b[1]};
    float e[2], o[2];
    merge11(ae, be, e); merge11(ao, bo, o);
    c[0] = e[0];
    c[1] = o[0]; c[2] = e[1]; s2(c[1], c[2]);
    c[3] = o[1];
}
__device__ __forceinline__ void merge33(const float* a, const float* b, float* c) {
    float ae[2] = {a[0], a[2]}, be[2] = {b[0], b[2]};
    float ao[1] = {a[1]},       bo[1] = {b[1]};
    float e[4], o[2];
    merge22(ae, be, e); merge11(ao, bo, o);
    c[0] = e[0];
    c[1] = o[0]; c[2] = e[1]; s2(c[1], c[2]);
    c[3] = o[1]; c[4] = e[2]; s2(c[3], c[4]);
    c[5] = e[3];
}
__device__ __forceinline__ void merge44(const float* a, const float* b, float* c) {
    float ae[2] = {a[0], a[2]}, be[2] = {b[0], b[2]};
    float ao[2] = {a[1], a[3]}, bo[2] = {b[1], b[3]};
    float e[4], o[4];
    merge22(ae, be, e); merge22(ao, bo, o);
    c[0] = e[0];
    c[1] = o[0]; c[2] = e[1]; s2(c[1], c[2]);
    c[3] = o[1]; c[4] = e[2]; s2(c[3], c[4]);
    c[5] = o[2]; c[6] = e[3]; s2(c[5], c[6]);
    c[7] = o[3];
}
__device__ __forceinline__ void merge55(const float* a, const float* b, float* c) {
    float ae[3] = {a[0], a[2], a[4]}, be[3] = {b[0], b[2], b[4]};
    float ao[2] = {a[1], a[3]},       bo[2] = {b[1], b[3]};
    float e[6], o[4];
    merge33(ae, be, e); merge22(ao, bo, o);
    c[0] = e[0];
#pragma unroll
    for (int i = 1; i <= 4; ++i) { c[2*i-1] = o[i-1]; c[2*i] = e[i]; s2(c[2*i-1], c[2*i]); }
    c[9] = e[5];
}
// Full merge of two sorted 9s into sorted 18 (ends dead-coded; only c[4..13] used).
__device__ __forceinline__ void merge99(const float* a, const float* b, float* c) {
    float ae[5] = {a[0], a[2], a[4], a[6], a[8]};
    float be[5] = {b[0], b[2], b[4], b[6], b[8]};
    float ao[4] = {a[1], a[3], a[5], a[7]};
    float bo[4] = {b[1], b[3], b[5], b[7]};
    float e[10], o[8];
    merge55(ae, be, e); merge44(ao, bo, o);
    c[0] = e[0];
#pragma unroll
    for (int i = 1; i <= 8; ++i) { c[2*i-1] = o[i-1]; c[2*i] = e[i]; s2(c[2*i-1], c[2*i]); }
    c[17] = e[9];
}

// 10th smallest of sorted X[0..8] ∪ sorted T[0..9]  (== median of the 27-window).
// Closed form: max( T[0], max_i min(X[i], T[9-i]) ).
__device__ __forceinline__ float select10(const float* X, const float* T) {
    float c0 = T[0];
    float c1 = fminf(X[0], T[9]);
    float c2 = fminf(X[1], T[8]);
    float c3 = fminf(X[2], T[7]);
    float c4 = fminf(X[3], T[6]);
    float c5 = fminf(X[4], T[5]);
    float c6 = fminf(X[5], T[4]);
    float c7 = fminf(X[6], T[3]);
    float c8 = fminf(X[7], T[2]);
    float c9 = fminf(X[8], T[1]);
    float m01 = fmaxf(c0, c1), m23 = fmaxf(c2, c3);
    float m45 = fmaxf(c4, c5), m67 = fmaxf(c6, c7);
    float m89 = fmaxf(c8, c9);
    return fmaxf(fmaxf(fmaxf(m01, m23), fmaxf(m45, m67)), m89);
}

__global__ void __launch_bounds__(256, 3)
median3d_kernel(const float* __restrict__ x, float* __restrict__ y) {
    const int w = threadIdx.x;          // 0..255
    const int h = blockIdx.x;           // 0..255
    const int d0 = blockIdx.y * D_CHUNK;

    // Clamped neighbor offsets (always-legal addresses) + fp masks for exact
    // zero padding. Masks are applied with FMUL on the (idle) fma pipe instead
    // of predicate/SEL traffic on the saturated alu pipe.
    const int ohm = (h > 0)         ? -W_DIM : 0;
    const int ohp = (h < H_DIM - 1) ?  W_DIM : 0;
    const int owm = (w > 0)         ? -1     : 0;
    const int owp = (w < W_DIM - 1) ?  1     : 0;
    const float fhm = (h > 0)         ? 1.0f : 0.0f;
    const float fhp = (h < H_DIM - 1) ? 1.0f : 0.0f;
    const float fwm = (w > 0)         ? 1.0f : 0.0f;
    const float fwp = (w < W_DIM - 1) ? 1.0f : 0.0f;
    const float m00 = fhm * fwm, m01 = fhm, m02 = fhm * fwp;
    const float m10 = fwm,                   m12 = fwp;
    const float m20 = fhp * fwm, m21 = fhp, m22 = fhp * fwp;

    const float* p0 = x + (size_t)h * W_DIM + w;
    float* o0 = y + (size_t)h * W_DIM + w;

#define LOADRAW(R, k)                                                   \
    do {                                                                \
        if ((k) < D_DIM) {                                              \
            const float* q = p0 + (size_t)(k) * PLANE;                  \
            R[0] = __ldg(q + ohm + owm) * m00;                          \
            R[1] = __ldg(q + ohm)       * m01;                          \
            R[2] = __ldg(q + ohm + owp) * m02;                          \
            R[3] = __ldg(q + owm)       * m10;                          \
            R[4] = __ldg(q);                                            \
            R[5] = __ldg(q + owp)       * m12;                          \
            R[6] = __ldg(q + ohp + owm) * m20;                          \
            R[7] = __ldg(q + ohp)       * m21;                          \
            R[8] = __ldg(q + ohp + owp) * m22;                          \
        } else {                                                        \
            R[0]=0.0f; R[1]=0.0f; R[2]=0.0f; R[3]=0.0f; R[4]=0.0f;      \
            R[5]=0.0f; R[6]=0.0f; R[7]=0.0f; R[8]=0.0f;                 \
        }                                                               \
    } while (0)

    float Pm[9], P0[9];                 // sorted planes d-1, d
    float cur1[9], cur2[9];             // raw planes d+1, d+2 (current pair)
    float nxt1[9], nxt2[9];             // raw planes d+3, d+4 (prefetched)
    float c[18];

    // plane d0-1 (zero pad if d0 == 0)
    if (d0 == 0) {
#pragma unroll
        for (int i = 0; i < 9; ++i) Pm[i] = 0.0f;
    } else {
        LOADRAW(Pm, d0 - 1);
        sort9(Pm);
    }
    // plane d0
    LOADRAW(P0, d0);
    sort9(P0);

    // raw planes for the first pair
    LOADRAW(cur1, d0 + 1);              // d0+1 <= 57, always valid
    LOADRAW(cur2, d0 + 2);              // d0+2 <= 58, always valid

#pragma unroll
    for (int pp = 0; pp < D_CHUNK / 2; ++pp) {
        const int d = d0 + 2 * pp;      // pair (d, d+1)

        // prefetch the NEXT pair's raw planes (latency hidden under the
        // sort/merge/select work below). LOADRAW zero-fills plane 64.
        if (pp + 1 < D_CHUNK / 2) {
            LOADRAW(nxt1, d + 3);
            LOADRAW(nxt2, d + 4);
        }

        sort9(cur1);                    // sorted plane d+1
        sort9(cur2);                    // sorted plane d+2 (zeros stay zeros)

        // shared sorted merge of planes (d, d+1); middle 10 = c[4..13]
        merge99(P0, cur1, c);

        // two independent rank selections (high ILP)
        o0[(size_t)d * PLANE]       = select10(Pm, c + 4);
        o0[(size_t)(d + 1) * PLANE] = select10(cur2, c + 4);

        // slide by 2 (register renaming under full unroll)
        if (pp + 1 < D_CHUNK / 2) {
#pragma unroll
            for (int i = 0; i < 9; ++i) {
                Pm[i] = cur1[i]; P0[i] = cur2[i];
                cur1[i] = nxt1[i]; cur2[i] = nxt2[i];
            }
        }
    }
#undef LOADRAW
}

extern "C" void kernel_launch(void* const* d_in, const int* in_sizes, int n_in,
                              void* d_out, int out_size) {
    const float* x = (const float*)d_in[0];
    float* y = (float*)d_out;
    dim3 block(256, 1, 1);
    dim3 grid(H_DIM, D_DIM / D_CHUNK, 1);  // (256, 8) = 2048 CTAs
    median3d_kernel<<<grid, block>>>(x, y);
}

// round 7
// speedup vs baseline: 1.0535x; 1.0535x over previous
#include <cuda_runtime.h>

#define D_DIM 64
#define H_DIM 256
#define W_DIM 256
#define PLANE (H_DIM * W_DIM)
#define D_CHUNK 16   // outputs per block along D (8 shared pairs)

// compare-exchange: a=min, b=max
__device__ __forceinline__ void s2(float& a, float& b) {
    float t = fminf(a, b);
    b = fmaxf(a, b);
    a = t;
}

// Optimal 9-input sorting network: 25 comparators, depth 7.
__device__ __forceinline__ void sort9(float* v) {
    s2(v[0],v[3]); s2(v[1],v[7]); s2(v[2],v[5]); s2(v[4],v[8]);
    s2(v[0],v[7]); s2(v[2],v[4]); s2(v[3],v[8]); s2(v[5],v[6]);
    s2(v[0],v[2]); s2(v[1],v[3]); s2(v[4],v[5]); s2(v[7],v[8]);
    s2(v[1],v[4]); s2(v[3],v[6]); s2(v[5],v[7]);
    s2(v[0],v[1]); s2(v[2],v[4]); s2(v[3],v[5]); s2(v[6],v[8]);
    s2(v[2],v[3]); s2(v[4],v[5]); s2(v[6],v[7]);
    s2(v[1],v[2]); s2(v[3],v[4]); s2(v[5],v[6]);
}

// ---- Batcher odd-even merges of two sorted arrays ----
__device__ __forceinline__ void merge11(const float* a, const float* b, float* c) {
    c[0] = a[0]; c[1] = b[0]; s2(c[0], c[1]);
}
__device__ __forceinline__ void merge22(const float* a, const float* b, float* c) {
    float ae[1] = {a[0]}, be[1] = {b[0]}, ao[1] = {a[1]}, bo[1] = {b[1]};
    float e[2], o[2];
    merge11(ae, be, e); merge11(ao, bo, o);
    c[0] = e[0];
    c[1] = o[0]; c[2] = e[1]; s2(c[1], c[2]);
    c[3] = o[1];
}
__device__ __forceinline__ void merge33(const float* a, const float* b, float* c) {
    float ae[2] = {a[0], a[2]}, be[2] = {b[0], b[2]};
    float ao[1] = {a[1]},       bo[1] = {b[1]};
    float e[4], o[2];
    merge22(ae, be, e); merge11(ao, bo, o);
    c[0] = e[0];
    c[1] = o[0]; c[2] = e[1]; s2(c[1], c[2]);
    c[3] = o[1]; c[4] = e[2]; s2(c[3], c[4]);
    c[5] = e[3];
}
__device__ __forceinline__ void merge44(const float* a, const float* b, float* c) {
    float ae[2] = {a[0], a[2]}, be[2] = {b[0], b[2]};
    float ao[2] = {a[1], a[3]}, bo[2] = {b[1], b[3]};
    float e[4], o[4];
    merge22(ae, be, e); merge22(ao, bo, o);
    c[0] = e[0];
    c[1] = o[0]; c[2] = e[1]; s2(c[1], c[2]);
    c[3] = o[1]; c[4] = e[2]; s2(c[3], c[4]);
    c[5] = o[2]; c[6] = e[3]; s2(c[5], c[6]);
    c[7] = o[3];
}
__device__ __forceinline__ void merge55(const float* a, const float* b, float* c) {
    float ae[3] = {a[0], a[2], a[4]}, be[3] = {b[0], b[2], b[4]};
    float ao[2] = {a[1], a[3]},       bo[2] = {b[1], b[3]};
    float e[6], o[4];
    merge33(ae, be, e); merge22(ao, bo, o);
    c[0] = e[0];
#pragma unroll
    for (int i = 1; i <= 4; ++i) { c[2*i-1] = o[i-1]; c[2*i] = e[i]; s2(c[2*i-1], c[2*i]); }
    c[9] = e[5];
}
// Full merge of two sorted 9s into sorted 18; only c[4..13] are consumed,
// comparators feeding only the ends are dead-coded by ptxas.
__device__ __forceinline__ void merge99(const float* a, const float* b, float* c) {
    float ae[5] = {a[0], a[2], a[4], a[6], a[8]};
    float be[5] = {b[0], b[2], b[4], b[6], b[8]};
    float ao[4] = {a[1], a[3], a[5], a[7]};
    float bo[4] = {b[1], b[3], b[5], b[7]};
    float e[10], o[8];
    merge55(ae, be, e); merge44(ao, bo, o);
    c[0] = e[0];
#pragma unroll
    for (int i = 1; i <= 8; ++i) { c[2*i-1] = o[i-1]; c[2*i] = e[i]; s2(c[2*i-1], c[2*i]); }
    c[17] = e[9];
}

// 10th smallest of sorted X[0..8] ∪ sorted T[0..9]  (== median of the 27-window).
// Closed form: max( T[0], max_i min(X[i], T[9-i]) ).
__device__ __forceinline__ float select10(const float* X, const float* T) {
    float c0 = T[0];
    float c1 = fminf(X[0], T[9]);
    float c2 = fminf(X[1], T[8]);
    float c3 = fminf(X[2], T[7]);
    float c4 = fminf(X[3], T[6]);
    float c5 = fminf(X[4], T[5]);
    float c6 = fminf(X[5], T[4]);
    float c7 = fminf(X[6], T[3]);
    float c8 = fminf(X[7], T[2]);
    float c9 = fminf(X[8], T[1]);
    float m01 = fmaxf(c0, c1), m23 = fmaxf(c2, c3);
    float m45 = fmaxf(c4, c5), m67 = fmaxf(c6, c7);
    float m89 = fmaxf(c8, c9);
    return fmaxf(fmaxf(fmaxf(m01, m23), fmaxf(m45, m67)), m89);
}

__global__ void __launch_bounds__(256, 4)
median3d_kernel(const float* __restrict__ x, float* __restrict__ y) {
    const int w = threadIdx.x;          // 0..255
    const int h = blockIdx.x;           // 0..255
    const int d0 = blockIdx.y * D_CHUNK;

    // Clamped neighbor offsets (always-legal addresses) + fp masks for exact
    // zero padding. Masks ride the near-idle fma pipe (FMUL), replacing
    // predicate/SEL traffic on the saturated alu pipe. Input is finite
    // (normal draws), so v*0 == 0 exactly.
    const int ohm = (h > 0)         ? -W_DIM : 0;
    const int ohp = (h < H_DIM - 1) ?  W_DIM : 0;
    const int owm = (w > 0)         ? -1     : 0;
    const int owp = (w < W_DIM - 1) ?  1     : 0;
    const float fhm = (h > 0)         ? 1.0f : 0.0f;
    const float fhp = (h < H_DIM - 1) ? 1.0f : 0.0f;
    const float fwm = (w > 0)         ? 1.0f : 0.0f;
    const float fwp = (w < W_DIM - 1) ? 1.0f : 0.0f;
    const float m00 = fhm * fwm, m01 = fhm, m02 = fhm * fwp;
    const float m10 = fwm,                   m12 = fwp;
    const float m20 = fhp * fwm, m21 = fhp, m22 = fhp * fwp;

    const float* p0 = x + (size_t)h * W_DIM + w;
    float* o0 = y + (size_t)h * W_DIM + w;

#define LOADSORT(P, k)                                                  \
    do {                                                                \
        const float* q = p0 + (size_t)(k) * PLANE;                      \
        P[0] = __ldg(q + ohm + owm) * m00;                              \
        P[1] = __ldg(q + ohm)       * m01;                              \
        P[2] = __ldg(q + ohm + owp) * m02;                              \
        P[3] = __ldg(q + owm)       * m10;                              \
        P[4] = __ldg(q);                                                \
        P[5] = __ldg(q + owp)       * m12;                              \
        P[6] = __ldg(q + ohp + owm) * m20;                              \
        P[7] = __ldg(q + ohp)       * m21;                              \
        P[8] = __ldg(q + ohp + owp) * m22;                              \
        sort9(P);                                                       \
    } while (0)

    float Pm[9], P0[9], P1[9], P2[9];   // sorted planes d-1, d, d+1, d+2
    float c[18];

    // plane d0-1 (zero pad if d0 == 0)
    if (d0 == 0) {
#pragma unroll
        for (int i = 0; i < 9; ++i) Pm[i] = 0.0f;
    } else {
        LOADSORT(Pm, d0 - 1);
    }
    // plane d0
    LOADSORT(P0, d0);

#pragma unroll
    for (int pp = 0; pp < D_CHUNK / 2; ++pp) {
        const int d = d0 + 2 * pp;      // pair (d, d+1); d <= 62

        LOADSORT(P1, d + 1);            // always exists (d+1 <= 63)

        if (d + 2 < D_DIM) {
            LOADSORT(P2, d + 2);
        } else {
#pragma unroll
            for (int i = 0; i < 9; ++i) P2[i] = 0.0f;   // plane 64 = zero pad
        }

        // shared sorted merge of planes (d, d+1); middle 10 = c[4..13]
        merge99(P0, P1, c);

        // two independent rank selections (high ILP)
        o0[(size_t)d * PLANE]       = select10(Pm, c + 4);
        o0[(size_t)(d + 1) * PLANE] = select10(P2, c + 4);

        // slide by 2 (register-renamed under full unroll)
#pragma unroll
        for (int i = 0; i < 9; ++i) { Pm[i] = P1[i]; P0[i] = P2[i]; }
    }
#undef LOADSORT
}

extern "C" void kernel_launch(void* const* d_in, const int* in_sizes, int n_in,
                              void* d_out, int out_size) {
    const float* x = (const float*)d_in[0];
    float* y = (float*)d_out;
    dim3 block(256, 1, 1);
    dim3 grid(H_DIM, D_DIM / D_CHUNK, 1);  // (256, 4) = 1024 CTAs
    median3d_kernel<<<grid, block>>>(x, y);
}